// round 14
// baseline (speedup 1.0000x reference)
#include <cuda_runtime.h>
#include <cuda_bf16.h>
#include <cuda_fp16.h>
#include <cstdint>

#define B_ 8
#define C_ 64
#define F_ 256
#define T_ 512
#define FT_ (F_*T_)                 /* 131072 */
#define NTHR_ 23
#define NPOSF 1048576.0

// ---------------- device scratch (static; no runtime allocation) ----------------
__device__ float  g_meanF[B_*C_*T_];
__device__ float  g_meanT[B_*C_*F_];
__device__ float  g_zt[B_*C_*T_];
__device__ float  g_zf[B_*C_*F_];
__device__ float  g_att[B_*F_*T_];
__device__ __half g_o16[(size_t)B_*C_*F_*T_];  // 128 MB pre-BN, layout [b][c][f][t], fp16
__device__ float  g_part[(size_t)32768*128];   // per (b,f,tt,wm) partials
__device__ float  g_part2[128*128];
__device__ float  g_thr[32];
__device__ float  g_pwT[24*68];                // transposed prefix sums pwT[j][c], row pad 68
__device__ __align__(16) unsigned short g_Wbh[64*136];  // W bf16 hi, padded [c][k]
__device__ __align__(16) unsigned short g_Wbl[64*136];  // W bf16 lo
__device__ float  g_scale[64];
__device__ float  g_shift[64];

__device__ __forceinline__ uint32_t smem_u32(const void* p) {
    uint32_t a;
    asm("{ .reg .u64 t; cvta.to.shared.u64 t, %1; cvt.u32.u64 %0, t; }" : "=r"(a) : "l"(p));
    return a;
}
__device__ __forceinline__ void ldsm_x4(uint32_t* r, uint32_t addr) {
    asm volatile("ldmatrix.sync.aligned.m8n8.x4.shared.b16 {%0,%1,%2,%3}, [%4];"
        : "=r"(r[0]), "=r"(r[1]), "=r"(r[2]), "=r"(r[3]) : "r"(addr));
}
__device__ __forceinline__ void mma16816(float* d, const uint32_t* a, const uint32_t* b) {
    asm volatile("mma.sync.aligned.m16n8k16.row.col.f32.bf16.bf16.f32 "
        "{%0,%1,%2,%3}, {%4,%5,%6,%7}, {%8,%9}, {%0,%1,%2,%3};"
        : "+f"(d[0]), "+f"(d[1]), "+f"(d[2]), "+f"(d[3])
        : "r"(a[0]), "r"(a[1]), "r"(a[2]), "r"(a[3]), "r"(b[0]), "r"(b[1]));
}
#define GBAR_ARRIVE(id) asm volatile("bar.arrive %0, 256;" :: "r"(id) : "memory")
#define GBAR_WAIT(id)   asm volatile("bar.sync %0, 256;"   :: "r"(id) : "memory")

// ---------------- K1: means over F/T per plane; block 512 = table prep ----------------
__global__ void k_reduce_prep(const float* __restrict__ x,
                              const float* __restrict__ wc2, const float* __restrict__ bc2,
                              const float* __restrict__ wo) {
    if (blockIdx.x == 512) {
        int tid = threadIdx.x;  // 256
        if (tid == 0) {
            double cnt = 0.0;
            for (int i = 1; i <= NTHR_; i++) { cnt += (double)i / 300.0; g_thr[i-1] = (float)cnt; }
        }
        if (tid < 64) {
            int c = tid;
            float s = 0.f;
            g_pwT[0*68 + c] = 0.f;
            for (int j = 1; j <= NTHR_; j++) { s += wc2[c*NTHR_ + (j-1)]; g_pwT[j*68 + c] = s; }
        }
        if (tid < 128) {
            int k = tid;  // augmented weight W[c][k]
            for (int c = 0; c < 64; c++) {
                float w;
                if (k < 64) w = wo[c*128 + k] + wo[c*128 + 64 + k] * bc2[k];
                else        w = wo[c*128 + k];
                __nv_bfloat16 hi = __float2bfloat16_rn(w);
                __nv_bfloat16 lo = __float2bfloat16_rn(w - __bfloat162float(hi));
                g_Wbh[c*136 + k] = __bfloat16_as_ushort(hi);
                g_Wbl[c*136 + k] = __bfloat16_as_ushort(lo);
            }
        }
        return;
    }
    int bc = blockIdx.x;
    const float* plane = x + (size_t)bc * FT_;
    int w = threadIdx.x >> 5, lane = threadIdx.x & 31;
    __shared__ float colp[8][512];

    float4 cacc[4];
    #pragma unroll
    for (int it = 0; it < 4; it++) cacc[it] = make_float4(0.f, 0.f, 0.f, 0.f);

    for (int f = w; f < F_; f += 8) {
        const float4* row = (const float4*)(plane + (size_t)f * T_);
        float rsum = 0.f;
        #pragma unroll
        for (int it = 0; it < 4; it++) {
            float4 v = row[lane + 32*it];
            rsum += (v.x + v.y) + (v.z + v.w);
            cacc[it].x += v.x; cacc[it].y += v.y; cacc[it].z += v.z; cacc[it].w += v.w;
        }
        #pragma unroll
        for (int off = 16; off > 0; off >>= 1) rsum += __shfl_xor_sync(0xffffffffu, rsum, off);
        if (lane == 0) g_meanT[(size_t)bc * F_ + f] = rsum * (1.f / (float)T_);
    }
    #pragma unroll
    for (int it = 0; it < 4; it++) ((float4*)colp[w])[lane + 32*it] = cacc[it];
    __syncthreads();
    for (int t = threadIdx.x; t < T_; t += 256) {
        float s = 0.f;
        #pragma unroll
        for (int ww = 0; ww < 8; ww++) s += colp[ww][t];
        g_meanF[(size_t)bc * T_ + t] = s * (1.f / (float)F_);
    }
}

// ---------------- K2: channel MLP -> zt, zf ----------------
__global__ void k_mlp(const float* __restrict__ w1, const float* __restrict__ b1,
                      const float* __restrict__ w2, const float* __restrict__ b2) {
    int l = blockIdx.x;
    int b = blockIdx.y;
    int c = threadIdx.x;
    bool isT = (l < T_);
    int L  = isT ? T_ : F_;
    int ll = isT ? l : l - T_;
    const float* src = isT ? g_meanF : g_meanT;
    float* dst       = isT ? g_zt    : g_zf;

    __shared__ float zs[64];
    __shared__ float hs[8];
    zs[c] = src[((size_t)b*64 + c) * L + ll];
    __syncthreads();
    if (c < 5) {
        float a = b1[c];
        #pragma unroll 8
        for (int i = 0; i < 64; i++) a += w1[c*64 + i] * zs[i];
        hs[c] = fmaxf(a, 0.f);
    }
    __syncthreads();
    float v = b2[c];
    #pragma unroll
    for (int j = 0; j < 5; j++) v += w2[c*5 + j] * hs[j];
    dst[((size_t)b*64 + c) * L + ll] = 1.f / (1.f + expf(-v));
}

// ---------------- K3: att_map ----------------
__global__ void k_attmap(const float* __restrict__ wc, const float* __restrict__ bc) {
    int b = blockIdx.y;
    int f0 = blockIdx.x * 8;
    int tid = threadIdx.x;
    int t0 = tid * 2;
    __shared__ float wcz[8][64];
    for (int i = tid; i < 512; i += 256) {
        int fi = i >> 6, c = i & 63;
        wcz[fi][c] = wc[c] * g_zf[((size_t)b*64 + c) * F_ + f0 + fi];
    }
    __syncthreads();
    float bcv = bc[0];
    float2 acc[8];
    #pragma unroll
    for (int fi = 0; fi < 8; fi++) acc[fi] = make_float2(bcv, bcv);
    const float* ztb = g_zt + (size_t)b * 64 * T_;
    for (int c = 0; c < 64; c++) {
        float2 z2 = *(const float2*)(ztb + (size_t)c * T_ + t0);
        #pragma unroll
        for (int fi = 0; fi < 8; fi++) {
            acc[fi].x += wcz[fi][c] * z2.x;
            acc[fi].y += wcz[fi][c] * z2.y;
        }
    }
    #pragma unroll
    for (int fi = 0; fi < 8; fi++)
        *(float2*)&g_att[((size_t)b*F_ + f0 + fi) * T_ + t0] = acc[fi];
}

// ---------------- K4: HMMA augmented GEMM, fp16 transposed-direct epilogue ----------------
#define AH_OFF 0u
#define AL_OFF 34816u
#define WH_OFF 69632u
#define WL_OFF 87040u
#define PW_OFF 104448u
#define THR_OFF 110976u
#define BOS_OFF 111104u
#define K4_SMEM 111360

__global__ void __launch_bounds__(256, 2) k_main(const float* __restrict__ x,
                                                 const float* __restrict__ bo) {
    extern __shared__ char sm[];
    const uint32_t s0 = smem_u32(sm);
    const int tid = threadIdx.x;
    const int lane = tid & 31;
    const int wid = tid >> 5;
    const int f = blockIdx.x, b = blockIdx.y;

    // ---- stage W hi/lo, pwT, thr, bos (once per CTA / 4 tiles) ----
    {
        const uint4* wh = (const uint4*)g_Wbh;
        const uint4* wl = (const uint4*)g_Wbl;
        uint4* dh = (uint4*)(sm + WH_OFF);
        uint4* dl = (uint4*)(sm + WL_OFF);
        for (int i = tid; i < 1088; i += 256) { dh[i] = wh[i]; dl[i] = wl[i]; }
        float* pwd = (float*)(sm + PW_OFF);
        for (int i = tid; i < 1632; i += 256) pwd[i] = g_pwT[i];
        if (tid < 32) ((float*)(sm + THR_OFF))[tid] = g_thr[tid];
        if (tid < 64) ((float*)(sm + BOS_OFF))[tid] = bo[tid];
    }

    const int t  = tid & 127;
    const int ch = (tid >> 7) * 32;
    const int g  = (tid >> 6) & 1;          // half-tile group
    const float* xbase = x + ((size_t)b*64*256 + f) * 512 + t;
    float a4[4];
    #pragma unroll
    for (int i = 0; i < 4; i++) a4[i] = g_att[((size_t)b*F_ + f) * T_ + i*128 + t];
    float xv[32];
    #pragma unroll
    for (int j = 0; j < 32; j++) xv[j] = __ldg(xbase + (size_t)(ch + j) * FT_);

    __syncthreads();   // W/pwT/thr staged (both groups)

    // warp HMMA geometry
    const int wm = wid & 3;
    const int wn = wid >> 2;
    const int quad = lane >> 3, r8 = lane & 7;
    const int arow = (quad & 1) ? 8 : 0;
    const int akof = (quad & 2) ? 16 : 0;
    const uint32_t aH0 = s0 + AH_OFF + (unsigned)(wm*32 + arow + r8) * 272u + akof;
    const uint32_t aH1 = aH0 + 16u * 272u;
    const int brow = (quad & 2) ? 8 : 0;
    const int bkof = (quad & 1) ? 16 : 0;
    const uint32_t bH0 = s0 + WH_OFF + (unsigned)(wn*32 + brow + r8) * 272u + bkof;
    const uint32_t bH1 = bH0 + 16u * 272u;

    const int BX = 3 + g, BY = 5 + g;       // group-local barrier ids
    GBAR_ARRIVE(BY);

    for (int tt = 0; tt < 4; tt++) {
        const int t0 = tt * 128;

        GBAR_WAIT(BY);   // group's ldsm of previous tile done -> safe to overwrite A half

        // ---- build A half-tile from prefetched xv ----
        {
            float a = a4[tt];
            const float* thrS = (const float*)(sm + THR_OFF);
            int Kc = 0;
            #pragma unroll
            for (int i = 0; i < NTHR_; i++) Kc += (a > thrS[i]) ? 1 : 0;
            const float* pwRow = (const float*)(sm + PW_OFF) + Kc * 68;

            char* rowH = sm + AH_OFF + (unsigned)t * 272u;
            char* rowL = sm + AL_OFF + (unsigned)t * 272u;
            #pragma unroll
            for (int c4 = 0; c4 < 32; c4 += 4) {
                int c = ch + c4;
                float4 pw4 = *(const float4*)(pwRow + c);
                float v[4], av[4];
                #pragma unroll
                for (int j = 0; j < 4; j++) v[j] = xv[c4 + j];
                av[0] = (a * pw4.x) * v[0];
                av[1] = (a * pw4.y) * v[1];
                av[2] = (a * pw4.z) * v[2];
                av[3] = (a * pw4.w) * v[3];
                unsigned hu[4], lu[4], au[4], alu2[4];
                #pragma unroll
                for (int j = 0; j < 4; j++) {
                    unsigned u = __float_as_uint(v[j]);
                    hu[j] = u & 0xFFFF0000u;
                    lu[j] = __float_as_uint(v[j] - __uint_as_float(hu[j]));
                    unsigned ua = __float_as_uint(av[j]);
                    au[j] = ua & 0xFFFF0000u;
                    alu2[j] = __float_as_uint(av[j] - __uint_as_float(au[j]));
                }
                uint2 ph  = make_uint2(__byte_perm(hu[0],  hu[1],  0x7632), __byte_perm(hu[2],  hu[3],  0x7632));
                uint2 pl  = make_uint2(__byte_perm(lu[0],  lu[1],  0x7632), __byte_perm(lu[2],  lu[3],  0x7632));
                uint2 pah = make_uint2(__byte_perm(au[0],  au[1],  0x7632), __byte_perm(au[2],  au[3],  0x7632));
                uint2 pal = make_uint2(__byte_perm(alu2[0],alu2[1],0x7632), __byte_perm(alu2[2],alu2[3],0x7632));
                *(uint2*)(rowH + c*2)        = ph;
                *(uint2*)(rowL + c*2)        = pl;
                *(uint2*)(rowH + 128 + c*2)  = pah;
                *(uint2*)(rowL + 128 + c*2)  = pal;
            }
        }
        GBAR_ARRIVE(BX);   // my STS done

        if (tt < 3) {
            const float* xn = xbase + (tt + 1) * 128;
            #pragma unroll
            for (int j = 0; j < 32; j++) xv[j] = __ldg(xn + (size_t)(ch + j) * FT_);
        }

        GBAR_WAIT(BX);   // group's STS done -> A half complete

        // ---- HMMA ----
        float acc[2][4][4];
        #pragma unroll
        for (int ms = 0; ms < 2; ms++)
            #pragma unroll
            for (int nb = 0; nb < 4; nb++)
                #pragma unroll
                for (int e = 0; e < 4; e++) acc[ms][nb][e] = 0.f;

        #pragma unroll 2
        for (int ks = 0; ks < 8; ks++) {
            const uint32_t ko = (unsigned)ks * 32u;
            uint32_t ah[2][4], al[2][4], bh[2][4], bl[2][4];
            ldsm_x4(ah[0], aH0 + ko);
            ldsm_x4(ah[1], aH1 + ko);
            ldsm_x4(al[0], aH0 + (AL_OFF - AH_OFF) + ko);
            ldsm_x4(al[1], aH1 + (AL_OFF - AH_OFF) + ko);
            ldsm_x4(bh[0], bH0 + ko);
            ldsm_x4(bh[1], bH1 + ko);
            ldsm_x4(bl[0], bH0 + (WL_OFF - WH_OFF) + ko);
            ldsm_x4(bl[1], bH1 + (WL_OFF - WH_OFF) + ko);
            #pragma unroll
            for (int ms = 0; ms < 2; ms++) {
                #pragma unroll
                for (int nb = 0; nb < 4; nb++) {
                    const uint32_t* bhp = &bh[nb >> 1][(nb & 1) * 2];
                    const uint32_t* blp = &bl[nb >> 1][(nb & 1) * 2];
                    mma16816(acc[ms][nb], ah[ms], bhp);
                    mma16816(acc[ms][nb], ah[ms], blp);
                    mma16816(acc[ms][nb], al[ms], bhp);
                }
            }
        }
        GBAR_ARRIVE(BY);   // my ldsm reads of A half done -> epilogue off the critical path

        // ---- fp16 transposed-direct epilogue: STG.U16 to g_o16[b][c][f][t] ----
        {
            const float* bosS = (const float*)(sm + BOS_OFF);
            const int r = lane >> 2;
            __half* gp = g_o16 + (size_t)b*64*FT_ + (size_t)f*512 + (unsigned)(t0 + wm*32 + r);
            #pragma unroll
            for (int nb = 0; nb < 4; nb++) {
                int c = wn*32 + nb*8 + 2*(lane & 3);
                float b0 = bosS[c], b1 = bosS[c+1];
                float v00 = acc[0][nb][0] + b0, v01 = acc[0][nb][1] + b1;
                float v02 = acc[0][nb][2] + b0, v03 = acc[0][nb][3] + b1;
                float v10 = acc[1][nb][0] + b0, v11 = acc[1][nb][1] + b1;
                float v12 = acc[1][nb][2] + b0, v13 = acc[1][nb][3] + b1;
                __half* p0 = gp + (size_t)c * FT_;
                __half* p1 = p0 + FT_;
                p0[0]  = __float2half_rn(v00);  p1[0]  = __float2half_rn(v01);
                p0[8]  = __float2half_rn(v02);  p1[8]  = __float2half_rn(v03);
                p0[16] = __float2half_rn(v10);  p1[16] = __float2half_rn(v11);
                p0[24] = __float2half_rn(v12);  p1[24] = __float2half_rn(v13);
                float s0c = (v00 + v02) + (v10 + v12);
                float s1c = (v01 + v03) + (v11 + v13);
                float q0c = (v00*v00 + v02*v02) + (v10*v10 + v12*v12);
                float q1c = (v01*v01 + v03*v03) + (v11*v11 + v13*v13);
                #pragma unroll
                for (int m = 4; m < 32; m <<= 1) {
                    s0c += __shfl_xor_sync(0xffffffffu, s0c, m);
                    s1c += __shfl_xor_sync(0xffffffffu, s1c, m);
                    q0c += __shfl_xor_sync(0xffffffffu, q0c, m);
                    q1c += __shfl_xor_sync(0xffffffffu, q1c, m);
                }
                if (lane < 4) {
                    size_t prow = ((((size_t)(b*256 + f))*4 + tt)*4 + wm) * 128;
                    g_part[prow + c]          = s0c;
                    g_part[prow + c + 1]      = s1c;
                    g_part[prow + 64 + c]     = q0c;
                    g_part[prow + 64 + c + 1] = q1c;
                }
            }
        }
    }
}

// ---------------- K5a: parallel partial reduce (128 CTAs, 256 rows each) ----------------
__global__ void k_stats1() {
    int j = threadIdx.x;           // 0..127
    size_t r0 = (size_t)blockIdx.x * 256;
    float s = 0.f;
    #pragma unroll 8
    for (int r = 0; r < 256; r++) s += g_part[(r0 + r)*128 + j];
    g_part2[blockIdx.x*128 + j] = s;
}

// ---------------- K5b: final stats (1 CTA, double) ----------------
__global__ void k_stats2(const float* __restrict__ gamma, const float* __restrict__ beta) {
    __shared__ double acc[128];
    int j = threadIdx.x;           // 0..127
    double s = 0.0;
    for (int i = 0; i < 128; i++) s += (double)g_part2[i*128 + j];
    acc[j] = s;
    __syncthreads();
    if (j < 64) {
        double mu  = acc[j] / NPOSF;
        double var = acc[64 + j] / NPOSF - mu * mu;
        float sc = gamma[j] * (float)(1.0 / sqrt(var + 1e-5));
        g_scale[j] = sc;
        g_shift[j] = beta[j] - (float)mu * sc;
    }
}

// ---------------- K6: normalize + ReLU, streaming fp16 -> fp32 ----------------
__global__ void k_norm(float* __restrict__ out) {
    __shared__ float sc[64], sh[64];
    if (threadIdx.x < 64) { sc[threadIdx.x] = g_scale[threadIdx.x]; sh[threadIdx.x] = g_shift[threadIdx.x]; }
    __syncthreads();
    const size_t n8 = (size_t)B_ * C_ * FT_ / 8;   // 8 halves per iteration
    const uint4* src = (const uint4*)g_o16;
    for (size_t i = (size_t)blockIdx.x * blockDim.x + threadIdx.x; i < n8;
         i += (size_t)gridDim.x * blockDim.x) {
        uint4 v = src[i];
        int c = (int)(i >> 14) & 63;   // FT_/8 = 16384 = 2^14 iters per channel
        float s = sc[c], t = sh[c];
        float2 f0 = __half22float2(*(__half2*)&v.x);
        float2 f1 = __half22float2(*(__half2*)&v.y);
        float2 f2 = __half22float2(*(__half2*)&v.z);
        float2 f3 = __half22float2(*(__half2*)&v.w);
        float4 o0, o1;
        o0.x = fmaxf(fmaf(f0.x, s, t), 0.f);
        o0.y = fmaxf(fmaf(f0.y, s, t), 0.f);
        o0.z = fmaxf(fmaf(f1.x, s, t), 0.f);
        o0.w = fmaxf(fmaf(f1.y, s, t), 0.f);
        o1.x = fmaxf(fmaf(f2.x, s, t), 0.f);
        o1.y = fmaxf(fmaf(f2.y, s, t), 0.f);
        o1.z = fmaxf(fmaf(f3.x, s, t), 0.f);
        o1.w = fmaxf(fmaf(f3.y, s, t), 0.f);
        ((float4*)out)[i*2]     = o0;
        ((float4*)out)[i*2 + 1] = o1;
    }
}

// ---------------- launch ----------------
extern "C" void kernel_launch(void* const* d_in, const int* in_sizes, int n_in,
                              void* d_out, int out_size) {
    const float* x     = (const float*)d_in[0];
    const float* w1    = (const float*)d_in[1];
    const float* b1    = (const float*)d_in[2];
    const float* w2    = (const float*)d_in[3];
    const float* b2    = (const float*)d_in[4];
    const float* wc    = (const float*)d_in[5];
    const float* bc    = (const float*)d_in[6];
    const float* wc2   = (const float*)d_in[7];
    const float* bc2   = (const float*)d_in[8];
    const float* wo    = (const float*)d_in[9];
    const float* bo    = (const float*)d_in[10];
    const float* gamma = (const float*)d_in[11];
    const float* beta  = (const float*)d_in[12];
    float* out = (float*)d_out;

    cudaFuncSetAttribute(k_main, cudaFuncAttributeMaxDynamicSharedMemorySize, K4_SMEM);

    k_reduce_prep<<<513, 256>>>(x, wc2, bc2, wo);
    k_mlp<<<dim3(768, B_), 64>>>(w1, b1, w2, b2);
    k_attmap<<<dim3(F_/8, B_), 256>>>(wc, bc);
    k_main<<<dim3(F_, B_), 256, K4_SMEM>>>(x, bo);
    k_stats1<<<128, 128>>>();
    k_stats2<<<1, 128>>>(gamma, beta);
    k_norm<<<4096, 256>>>(out);
}

// round 16
// speedup vs baseline: 1.6216x; 1.6216x over previous
#include <cuda_runtime.h>
#include <cuda_fp16.h>
#include <cstdint>

#define B_ 8
#define C_ 64
#define F_ 256
#define T_ 512
#define FT_ (F_*T_)                 /* 131072 */
#define NTHR_ 23
#define NPOSF 1048576.0

// ---------------- device scratch (static; no runtime allocation) ----------------
__device__ float  g_meanF[B_*C_*T_];
__device__ float  g_meanT[B_*C_*F_];
__device__ float  g_zt[B_*C_*T_];
__device__ float  g_zf[B_*C_*F_];
__device__ float  g_att[B_*F_*T_];
__device__ float  g_o[(size_t)B_*C_*F_*T_];   // 256 MB pre-BN, layout [b][c][f][t], fp32
__device__ float  g_part[(size_t)32768*128];  // per (b,f,tt,wm) partials
__device__ float  g_part2[128*128];
__device__ float  g_thr[32];
__device__ float  g_pwT[24*68];               // transposed prefix sums pwT[j][c], row pad 68
__device__ __align__(16) unsigned short g_Wh[64*136];  // W fp16 (RN), padded [c][k]
__device__ float  g_scale[64];
__device__ float  g_shift[64];

__device__ __forceinline__ uint32_t smem_u32(const void* p) {
    uint32_t a;
    asm("{ .reg .u64 t; cvta.to.shared.u64 t, %1; cvt.u32.u64 %0, t; }" : "=r"(a) : "l"(p));
    return a;
}
__device__ __forceinline__ void ldsm_x4(uint32_t* r, uint32_t addr) {
    asm volatile("ldmatrix.sync.aligned.m8n8.x4.shared.b16 {%0,%1,%2,%3}, [%4];"
        : "=r"(r[0]), "=r"(r[1]), "=r"(r[2]), "=r"(r[3]) : "r"(addr));
}
__device__ __forceinline__ void mma16816(float* d, const uint32_t* a, const uint32_t* b) {
    asm volatile("mma.sync.aligned.m16n8k16.row.col.f32.f16.f16.f32 "
        "{%0,%1,%2,%3}, {%4,%5,%6,%7}, {%8,%9}, {%0,%1,%2,%3};"
        : "+f"(d[0]), "+f"(d[1]), "+f"(d[2]), "+f"(d[3])
        : "r"(a[0]), "r"(a[1]), "r"(a[2]), "r"(a[3]), "r"(b[0]), "r"(b[1]));
}
__device__ __forceinline__ unsigned pack_h2(float lo, float hi) {
    __half2 h = __floats2half2_rn(lo, hi);   // x=lo (low 16 bits), y=hi
    return *(unsigned*)&h;
}
#define GBAR_ARRIVE(id) asm volatile("bar.arrive %0, 256;" :: "r"(id) : "memory")
#define GBAR_WAIT(id)   asm volatile("bar.sync %0, 256;"   :: "r"(id) : "memory")

// ---------------- K1: means over F/T per plane; block 512 = table prep ----------------
__global__ void k_reduce_prep(const float* __restrict__ x,
                              const float* __restrict__ wc2, const float* __restrict__ bc2,
                              const float* __restrict__ wo) {
    if (blockIdx.x == 512) {
        int tid = threadIdx.x;  // 256
        if (tid == 0) {
            double cnt = 0.0;
            for (int i = 1; i <= NTHR_; i++) { cnt += (double)i / 300.0; g_thr[i-1] = (float)cnt; }
        }
        if (tid < 64) {
            int c = tid;
            float s = 0.f;
            g_pwT[0*68 + c] = 0.f;
            for (int j = 1; j <= NTHR_; j++) { s += wc2[c*NTHR_ + (j-1)]; g_pwT[j*68 + c] = s; }
        }
        if (tid < 128) {
            int k = tid;  // augmented weight W[c][k], single RN fp16
            for (int c = 0; c < 64; c++) {
                float w;
                if (k < 64) w = wo[c*128 + k] + wo[c*128 + 64 + k] * bc2[k];
                else        w = wo[c*128 + k];
                __half h = __float2half_rn(w);
                g_Wh[c*136 + k] = *(unsigned short*)&h;
            }
        }
        return;
    }
    int bc = blockIdx.x;
    const float* plane = x + (size_t)bc * FT_;
    int w = threadIdx.x >> 5, lane = threadIdx.x & 31;
    __shared__ float colp[8][512];

    float4 cacc[4];
    #pragma unroll
    for (int it = 0; it < 4; it++) cacc[it] = make_float4(0.f, 0.f, 0.f, 0.f);

    for (int f = w; f < F_; f += 8) {
        const float4* row = (const float4*)(plane + (size_t)f * T_);
        float rsum = 0.f;
        #pragma unroll
        for (int it = 0; it < 4; it++) {
            float4 v = row[lane + 32*it];
            rsum += (v.x + v.y) + (v.z + v.w);
            cacc[it].x += v.x; cacc[it].y += v.y; cacc[it].z += v.z; cacc[it].w += v.w;
        }
        #pragma unroll
        for (int off = 16; off > 0; off >>= 1) rsum += __shfl_xor_sync(0xffffffffu, rsum, off);
        if (lane == 0) g_meanT[(size_t)bc * F_ + f] = rsum * (1.f / (float)T_);
    }
    #pragma unroll
    for (int it = 0; it < 4; it++) ((float4*)colp[w])[lane + 32*it] = cacc[it];
    __syncthreads();
    for (int t = threadIdx.x; t < T_; t += 256) {
        float s = 0.f;
        #pragma unroll
        for (int ww = 0; ww < 8; ww++) s += colp[ww][t];
        g_meanF[(size_t)bc * T_ + t] = s * (1.f / (float)F_);
    }
}

// ---------------- K2: channel MLP -> zt, zf ----------------
__global__ void k_mlp(const float* __restrict__ w1, const float* __restrict__ b1,
                      const float* __restrict__ w2, const float* __restrict__ b2) {
    int l = blockIdx.x;
    int b = blockIdx.y;
    int c = threadIdx.x;
    bool isT = (l < T_);
    int L  = isT ? T_ : F_;
    int ll = isT ? l : l - T_;
    const float* src = isT ? g_meanF : g_meanT;
    float* dst       = isT ? g_zt    : g_zf;

    __shared__ float zs[64];
    __shared__ float hs[8];
    zs[c] = src[((size_t)b*64 + c) * L + ll];
    __syncthreads();
    if (c < 5) {
        float a = b1[c];
        #pragma unroll 8
        for (int i = 0; i < 64; i++) a += w1[c*64 + i] * zs[i];
        hs[c] = fmaxf(a, 0.f);
    }
    __syncthreads();
    float v = b2[c];
    #pragma unroll
    for (int j = 0; j < 5; j++) v += w2[c*5 + j] * hs[j];
    dst[((size_t)b*64 + c) * L + ll] = 1.f / (1.f + expf(-v));
}

// ---------------- K3: att_map ----------------
__global__ void k_attmap(const float* __restrict__ wc, const float* __restrict__ bc) {
    int b = blockIdx.y;
    int f0 = blockIdx.x * 8;
    int tid = threadIdx.x;
    int t0 = tid * 2;
    __shared__ float wcz[8][64];
    for (int i = tid; i < 512; i += 256) {
        int fi = i >> 6, c = i & 63;
        wcz[fi][c] = wc[c] * g_zf[((size_t)b*64 + c) * F_ + f0 + fi];
    }
    __syncthreads();
    float bcv = bc[0];
    float2 acc[8];
    #pragma unroll
    for (int fi = 0; fi < 8; fi++) acc[fi] = make_float2(bcv, bcv);
    const float* ztb = g_zt + (size_t)b * 64 * T_;
    for (int c = 0; c < 64; c++) {
        float2 z2 = *(const float2*)(ztb + (size_t)c * T_ + t0);
        #pragma unroll
        for (int fi = 0; fi < 8; fi++) {
            acc[fi].x += wcz[fi][c] * z2.x;
            acc[fi].y += wcz[fi][c] * z2.y;
        }
    }
    #pragma unroll
    for (int fi = 0; fi < 8; fi++)
        *(float2*)&g_att[((size_t)b*F_ + f0 + fi) * T_ + t0] = acc[fi];
}

// ---------------- K4: single-pass fp16 HMMA GEMM, 3 CTAs/SM ----------------
#define AH_OFF 0u
#define WH_OFF 34816u
#define PW_OFF 52224u
#define THR_OFF 58752u
#define BOS_OFF 58880u
#define K4_SMEM 59392

__global__ void __launch_bounds__(256, 3) k_main(const float* __restrict__ x,
                                                 const float* __restrict__ bo) {
    extern __shared__ char sm[];
    const uint32_t s0 = smem_u32(sm);
    const int tid = threadIdx.x;
    const int lane = tid & 31;
    const int wid = tid >> 5;
    const int f = blockIdx.x, b = blockIdx.y;

    // ---- stage W, pwT, thr, bos (once per CTA / 4 tiles) ----
    {
        const uint4* ws = (const uint4*)g_Wh;
        uint4* wd = (uint4*)(sm + WH_OFF);
        for (int i = tid; i < 1088; i += 256) wd[i] = ws[i];
        float* pwd = (float*)(sm + PW_OFF);
        for (int i = tid; i < 1632; i += 256) pwd[i] = g_pwT[i];
        if (tid < 32) ((float*)(sm + THR_OFF))[tid] = g_thr[tid];
        if (tid < 64) ((float*)(sm + BOS_OFF))[tid] = bo[tid];
    }

    const int t  = tid & 127;
    const int ch = (tid >> 7) * 32;
    const int g  = (tid >> 6) & 1;          // half-tile group
    const float* xbase = x + ((size_t)b*64*256 + f) * 512 + t;
    float a4[4];
    #pragma unroll
    for (int i = 0; i < 4; i++) a4[i] = g_att[((size_t)b*F_ + f) * T_ + i*128 + t];

    __syncthreads();   // W/pwT/thr staged (both groups)

    // warp HMMA geometry
    const int wm = wid & 3;
    const int wn = wid >> 2;
    const int quad = lane >> 3, r8 = lane & 7;
    const int arow = (quad & 1) ? 8 : 0;
    const int akof = (quad & 2) ? 16 : 0;
    const uint32_t aH0 = s0 + AH_OFF + (unsigned)(wm*32 + arow + r8) * 272u + akof;
    const uint32_t aH1 = aH0 + 16u * 272u;
    const int brow = (quad & 2) ? 8 : 0;
    const int bkof = (quad & 1) ? 16 : 0;
    const uint32_t bH0 = s0 + WH_OFF + (unsigned)(wn*32 + brow + r8) * 272u + bkof;
    const uint32_t bH1 = bH0 + 16u * 272u;

    const int BX = 3 + g, BY = 5 + g;       // group-local barrier ids
    GBAR_ARRIVE(BY);

    for (int tt = 0; tt < 4; tt++) {
        const int t0 = tt * 128;

        GBAR_WAIT(BY);   // group's ldsm of previous tile done -> safe to overwrite A half

        // ---- build A half-tile: RN fp16, direct LDG (occupancy hides latency) ----
        {
            float a = a4[tt];
            const float* thrS = (const float*)(sm + THR_OFF);
            int Kc = 0;
            #pragma unroll
            for (int i = 0; i < NTHR_; i++) Kc += (a > thrS[i]) ? 1 : 0;
            const float* pwRow = (const float*)(sm + PW_OFF) + Kc * 68;
            const float* xp = xbase + t0;

            char* rowH = sm + AH_OFF + (unsigned)t * 272u;
            #pragma unroll
            for (int c4 = 0; c4 < 32; c4 += 4) {
                int c = ch + c4;
                float4 pw4 = *(const float4*)(pwRow + c);
                float v[4], av[4];
                #pragma unroll
                for (int j = 0; j < 4; j++) v[j] = __ldg(xp + (size_t)(c + j) * FT_);
                av[0] = (a * pw4.x) * v[0];
                av[1] = (a * pw4.y) * v[1];
                av[2] = (a * pw4.z) * v[2];
                av[3] = (a * pw4.w) * v[3];
                uint2 ph  = make_uint2(pack_h2(v[0],  v[1]),  pack_h2(v[2],  v[3]));
                uint2 pah = make_uint2(pack_h2(av[0], av[1]), pack_h2(av[2], av[3]));
                *(uint2*)(rowH + c*2)       = ph;
                *(uint2*)(rowH + 128 + c*2) = pah;
            }
        }
        GBAR_ARRIVE(BX);   // my STS done
        GBAR_WAIT(BX);     // group's STS done -> A half complete

        // ---- HMMA: single fp16 pass, 64 mma ----
        float acc[2][4][4];
        #pragma unroll
        for (int ms = 0; ms < 2; ms++)
            #pragma unroll
            for (int nb = 0; nb < 4; nb++)
                #pragma unroll
                for (int e = 0; e < 4; e++) acc[ms][nb][e] = 0.f;

        #pragma unroll 4
        for (int ks = 0; ks < 8; ks++) {
            const uint32_t ko = (unsigned)ks * 32u;
            uint32_t ah[2][4], bh[2][4];
            ldsm_x4(ah[0], aH0 + ko);
            ldsm_x4(ah[1], aH1 + ko);
            ldsm_x4(bh[0], bH0 + ko);
            ldsm_x4(bh[1], bH1 + ko);
            #pragma unroll
            for (int ms = 0; ms < 2; ms++) {
                #pragma unroll
                for (int nb = 0; nb < 4; nb++) {
                    mma16816(acc[ms][nb], ah[ms], &bh[nb >> 1][(nb & 1) * 2]);
                }
            }
        }
        GBAR_ARRIVE(BY);   // my ldsm reads of A half done -> epilogue off the critical path

        // ---- fp32 transposed-direct epilogue: scalar STG to g_o[b][c][f][t] ----
        {
            const float* bosS = (const float*)(sm + BOS_OFF);
            const int r = lane >> 2;
            float* gp = g_o + (size_t)b*64*FT_ + (size_t)f*512 + (unsigned)(t0 + wm*32 + r);
            #pragma unroll
            for (int nb = 0; nb < 4; nb++) {
                int c = wn*32 + nb*8 + 2*(lane & 3);
                float b0 = bosS[c], b1 = bosS[c+1];
                float v00 = acc[0][nb][0] + b0, v01 = acc[0][nb][1] + b1;
                float v02 = acc[0][nb][2] + b0, v03 = acc[0][nb][3] + b1;
                float v10 = acc[1][nb][0] + b0, v11 = acc[1][nb][1] + b1;
                float v12 = acc[1][nb][2] + b0, v13 = acc[1][nb][3] + b1;
                float* p0 = gp + (size_t)c * FT_;
                float* p1 = p0 + FT_;
                p0[0]  = v00;  p1[0]  = v01;
                p0[8]  = v02;  p1[8]  = v03;
                p0[16] = v10;  p1[16] = v11;
                p0[24] = v12;  p1[24] = v13;
                float s0c = (v00 + v02) + (v10 + v12);
                float s1c = (v01 + v03) + (v11 + v13);
                float q0c = (v00*v00 + v02*v02) + (v10*v10 + v12*v12);
                float q1c = (v01*v01 + v03*v03) + (v11*v11 + v13*v13);
                #pragma unroll
                for (int m = 4; m < 32; m <<= 1) {
                    s0c += __shfl_xor_sync(0xffffffffu, s0c, m);
                    s1c += __shfl_xor_sync(0xffffffffu, s1c, m);
                    q0c += __shfl_xor_sync(0xffffffffu, q0c, m);
                    q1c += __shfl_xor_sync(0xffffffffu, q1c, m);
                }
                if (lane < 4) {
                    size_t prow = ((((size_t)(b*256 + f))*4 + tt)*4 + wm) * 128;
                    g_part[prow + c]          = s0c;
                    g_part[prow + c + 1]      = s1c;
                    g_part[prow + 64 + c]     = q0c;
                    g_part[prow + 64 + c + 1] = q1c;
                }
            }
        }
    }
}

// ---------------- K5a: parallel partial reduce (128 CTAs, 256 rows each) ----------------
__global__ void k_stats1() {
    int j = threadIdx.x;           // 0..127
    size_t r0 = (size_t)blockIdx.x * 256;
    float s = 0.f;
    #pragma unroll 8
    for (int r = 0; r < 256; r++) s += g_part[(r0 + r)*128 + j];
    g_part2[blockIdx.x*128 + j] = s;
}

// ---------------- K5b: final stats (1 CTA, double) ----------------
__global__ void k_stats2(const float* __restrict__ gamma, const float* __restrict__ beta) {
    __shared__ double acc[128];
    int j = threadIdx.x;           // 0..127
    double s = 0.0;
    for (int i = 0; i < 128; i++) s += (double)g_part2[i*128 + j];
    acc[j] = s;
    __syncthreads();
    if (j < 64) {
        double mu  = acc[j] / NPOSF;
        double var = acc[64 + j] / NPOSF - mu * mu;
        float sc = gamma[j] * (float)(1.0 / sqrt(var + 1e-5));
        g_scale[j] = sc;
        g_shift[j] = beta[j] - (float)mu * sc;
    }
}

// ---------------- K6: normalize + ReLU, pure streaming ----------------
__global__ void k_norm(float* __restrict__ out) {
    __shared__ float sc[64], sh[64];
    if (threadIdx.x < 64) { sc[threadIdx.x] = g_scale[threadIdx.x]; sh[threadIdx.x] = g_shift[threadIdx.x]; }
    __syncthreads();
    const size_t n4 = (size_t)B_ * C_ * FT_ / 4;
    const float4* src = (const float4*)g_o;
    float4* dst = (float4*)out;
    for (size_t i = (size_t)blockIdx.x * blockDim.x + threadIdx.x; i < n4;
         i += (size_t)gridDim.x * blockDim.x) {
        float4 v = src[i];
        int c = (int)(i >> 15) & 63;   // FT_/4 = 32768 = 2^15
        float s = sc[c], t = sh[c];
        v.x = fmaxf(fmaf(v.x, s, t), 0.f);
        v.y = fmaxf(fmaf(v.y, s, t), 0.f);
        v.z = fmaxf(fmaf(v.z, s, t), 0.f);
        v.w = fmaxf(fmaf(v.w, s, t), 0.f);
        dst[i] = v;
    }
}

// ---------------- launch ----------------
extern "C" void kernel_launch(void* const* d_in, const int* in_sizes, int n_in,
                              void* d_out, int out_size) {
    const float* x     = (const float*)d_in[0];
    const float* w1    = (const float*)d_in[1];
    const float* b1    = (const float*)d_in[2];
    const float* w2    = (const float*)d_in[3];
    const float* b2    = (const float*)d_in[4];
    const float* wc    = (const float*)d_in[5];
    const float* bc    = (const float*)d_in[6];
    const float* wc2   = (const float*)d_in[7];
    const float* bc2   = (const float*)d_in[8];
    const float* wo    = (const float*)d_in[9];
    const float* bo    = (const float*)d_in[10];
    const float* gamma = (const float*)d_in[11];
    const float* beta  = (const float*)d_in[12];
    float* out = (float*)d_out;

    cudaFuncSetAttribute(k_main, cudaFuncAttributeMaxDynamicSharedMemorySize, K4_SMEM);

    k_reduce_prep<<<513, 256>>>(x, wc2, bc2, wo);
    k_mlp<<<dim3(768, B_), 64>>>(w1, b1, w2, b2);
    k_attmap<<<dim3(F_/8, B_), 256>>>(wc, bc);
    k_main<<<dim3(F_, B_), 256, K4_SMEM>>>(x, bo);
    k_stats1<<<128, 128>>>();
    k_stats2<<<1, 128>>>(gamma, beta);
    k_norm<<<4096, 256>>>(out);
}

// round 17
// speedup vs baseline: 1.6712x; 1.0306x over previous
#include <cuda_runtime.h>
#include <cuda_fp16.h>
#include <cstdint>

#define B_ 8
#define C_ 64
#define F_ 256
#define T_ 512
#define FT_ (F_*T_)                 /* 131072 */
#define NTHR_ 23
#define NPOSF 1048576.0

// ---------------- device scratch (static; no runtime allocation) ----------------
__device__ float  g_meanF[B_*C_*T_];
__device__ float  g_meanT[B_*C_*F_];
__device__ float  g_zt[B_*C_*T_];
__device__ float  g_zf[B_*C_*F_];
__device__ float  g_att[B_*F_*T_];
__device__ __half g_o16[(size_t)B_*C_*F_*T_];  // 128 MB pre-BN, layout [b][f][t][c], fp16
__device__ float  g_part[(size_t)32768*128];   // per (b,f,tt,wm) partials
__device__ float  g_part2[128*128];
__device__ float  g_thr[32];
__device__ float  g_pwT[24*68];                // transposed prefix sums pwT[j][c], row pad 68
__device__ __align__(16) unsigned short g_Wh[64*136];  // W fp16 (RN), padded [c][k]
__device__ float  g_scale[64];
__device__ float  g_shift[64];

__device__ __forceinline__ uint32_t smem_u32(const void* p) {
    uint32_t a;
    asm("{ .reg .u64 t; cvta.to.shared.u64 t, %1; cvt.u32.u64 %0, t; }" : "=r"(a) : "l"(p));
    return a;
}
__device__ __forceinline__ void ldsm_x4(uint32_t* r, uint32_t addr) {
    asm volatile("ldmatrix.sync.aligned.m8n8.x4.shared.b16 {%0,%1,%2,%3}, [%4];"
        : "=r"(r[0]), "=r"(r[1]), "=r"(r[2]), "=r"(r[3]) : "r"(addr));
}
__device__ __forceinline__ void mma16816(float* d, const uint32_t* a, const uint32_t* b) {
    asm volatile("mma.sync.aligned.m16n8k16.row.col.f32.f16.f16.f32 "
        "{%0,%1,%2,%3}, {%4,%5,%6,%7}, {%8,%9}, {%0,%1,%2,%3};"
        : "+f"(d[0]), "+f"(d[1]), "+f"(d[2]), "+f"(d[3])
        : "r"(a[0]), "r"(a[1]), "r"(a[2]), "r"(a[3]), "r"(b[0]), "r"(b[1]));
}
__device__ __forceinline__ unsigned pack_h2(float lo, float hi) {
    __half2 h = __floats2half2_rn(lo, hi);
    return *(unsigned*)&h;
}
#define GBAR_ARRIVE(id) asm volatile("bar.arrive %0, 256;" :: "r"(id) : "memory")
#define GBAR_WAIT(id)   asm volatile("bar.sync %0, 256;"   :: "r"(id) : "memory")

// ---------------- K1: means over F/T per plane; block 512 = table prep ----------------
__global__ void k_reduce_prep(const float* __restrict__ x,
                              const float* __restrict__ wc2, const float* __restrict__ bc2,
                              const float* __restrict__ wo) {
    if (blockIdx.x == 512) {
        int tid = threadIdx.x;  // 256
        if (tid == 0) {
            double cnt = 0.0;
            for (int i = 1; i <= NTHR_; i++) { cnt += (double)i / 300.0; g_thr[i-1] = (float)cnt; }
        }
        if (tid < 64) {
            int c = tid;
            float s = 0.f;
            g_pwT[0*68 + c] = 0.f;
            for (int j = 1; j <= NTHR_; j++) { s += wc2[c*NTHR_ + (j-1)]; g_pwT[j*68 + c] = s; }
        }
        if (tid < 128) {
            int k = tid;  // augmented weight W[c][k], single RN fp16
            for (int c = 0; c < 64; c++) {
                float w;
                if (k < 64) w = wo[c*128 + k] + wo[c*128 + 64 + k] * bc2[k];
                else        w = wo[c*128 + k];
                __half h = __float2half_rn(w);
                g_Wh[c*136 + k] = *(unsigned short*)&h;
            }
        }
        return;
    }
    int bc = blockIdx.x;
    const float* plane = x + (size_t)bc * FT_;
    int w = threadIdx.x >> 5, lane = threadIdx.x & 31;
    __shared__ float colp[8][512];

    float4 cacc[4];
    #pragma unroll
    for (int it = 0; it < 4; it++) cacc[it] = make_float4(0.f, 0.f, 0.f, 0.f);

    for (int f = w; f < F_; f += 8) {
        const float4* row = (const float4*)(plane + (size_t)f * T_);
        float rsum = 0.f;
        #pragma unroll
        for (int it = 0; it < 4; it++) {
            float4 v = row[lane + 32*it];
            rsum += (v.x + v.y) + (v.z + v.w);
            cacc[it].x += v.x; cacc[it].y += v.y; cacc[it].z += v.z; cacc[it].w += v.w;
        }
        #pragma unroll
        for (int off = 16; off > 0; off >>= 1) rsum += __shfl_xor_sync(0xffffffffu, rsum, off);
        if (lane == 0) g_meanT[(size_t)bc * F_ + f] = rsum * (1.f / (float)T_);
    }
    #pragma unroll
    for (int it = 0; it < 4; it++) ((float4*)colp[w])[lane + 32*it] = cacc[it];
    __syncthreads();
    for (int t = threadIdx.x; t < T_; t += 256) {
        float s = 0.f;
        #pragma unroll
        for (int ww = 0; ww < 8; ww++) s += colp[ww][t];
        g_meanF[(size_t)bc * T_ + t] = s * (1.f / (float)F_);
    }
}

// ---------------- K2: channel MLP -> zt, zf ----------------
__global__ void k_mlp(const float* __restrict__ w1, const float* __restrict__ b1,
                      const float* __restrict__ w2, const float* __restrict__ b2) {
    int l = blockIdx.x;
    int b = blockIdx.y;
    int c = threadIdx.x;
    bool isT = (l < T_);
    int L  = isT ? T_ : F_;
    int ll = isT ? l : l - T_;
    const float* src = isT ? g_meanF : g_meanT;
    float* dst       = isT ? g_zt    : g_zf;

    __shared__ float zs[64];
    __shared__ float hs[8];
    zs[c] = src[((size_t)b*64 + c) * L + ll];
    __syncthreads();
    if (c < 5) {
        float a = b1[c];
        #pragma unroll 8
        for (int i = 0; i < 64; i++) a += w1[c*64 + i] * zs[i];
        hs[c] = fmaxf(a, 0.f);
    }
    __syncthreads();
    float v = b2[c];
    #pragma unroll
    for (int j = 0; j < 5; j++) v += w2[c*5 + j] * hs[j];
    dst[((size_t)b*64 + c) * L + ll] = 1.f / (1.f + expf(-v));
}

// ---------------- K3: att_map ----------------
__global__ void k_attmap(const float* __restrict__ wc, const float* __restrict__ bc) {
    int b = blockIdx.y;
    int f0 = blockIdx.x * 8;
    int tid = threadIdx.x;
    int t0 = tid * 2;
    __shared__ float wcz[8][64];
    for (int i = tid; i < 512; i += 256) {
        int fi = i >> 6, c = i & 63;
        wcz[fi][c] = wc[c] * g_zf[((size_t)b*64 + c) * F_ + f0 + fi];
    }
    __syncthreads();
    float bcv = bc[0];
    float2 acc[8];
    #pragma unroll
    for (int fi = 0; fi < 8; fi++) acc[fi] = make_float2(bcv, bcv);
    const float* ztb = g_zt + (size_t)b * 64 * T_;
    for (int c = 0; c < 64; c++) {
        float2 z2 = *(const float2*)(ztb + (size_t)c * T_ + t0);
        #pragma unroll
        for (int fi = 0; fi < 8; fi++) {
            acc[fi].x += wcz[fi][c] * z2.x;
            acc[fi].y += wcz[fi][c] * z2.y;
        }
    }
    #pragma unroll
    for (int fi = 0; fi < 8; fi++)
        *(float2*)&g_att[((size_t)b*F_ + f0 + fi) * T_ + t0] = acc[fi];
}

// ---------------- K4: single-pass fp16 HMMA GEMM, 3 CTAs/SM, fp16 half2 epilogue ----------------
#define AH_OFF 0u
#define WH_OFF 34816u
#define PW_OFF 52224u
#define THR_OFF 58752u
#define BOS_OFF 58880u
#define K4_SMEM 59392

__global__ void __launch_bounds__(256, 3) k_main(const float* __restrict__ x,
                                                 const float* __restrict__ bo) {
    extern __shared__ char sm[];
    const uint32_t s0 = smem_u32(sm);
    const int tid = threadIdx.x;
    const int lane = tid & 31;
    const int wid = tid >> 5;
    const int f = blockIdx.x, b = blockIdx.y;

    // ---- stage W, pwT, thr, bos (once per CTA / 4 tiles) ----
    {
        const uint4* ws = (const uint4*)g_Wh;
        uint4* wd = (uint4*)(sm + WH_OFF);
        for (int i = tid; i < 1088; i += 256) wd[i] = ws[i];
        float* pwd = (float*)(sm + PW_OFF);
        for (int i = tid; i < 1632; i += 256) pwd[i] = g_pwT[i];
        if (tid < 32) ((float*)(sm + THR_OFF))[tid] = g_thr[tid];
        if (tid < 64) ((float*)(sm + BOS_OFF))[tid] = bo[tid];
    }

    const int t  = tid & 127;
    const int ch = (tid >> 7) * 32;
    const int g  = (tid >> 6) & 1;          // half-tile group
    const float* xbase = x + ((size_t)b*64*256 + f) * 512 + t;
    float a4[4];
    #pragma unroll
    for (int i = 0; i < 4; i++) a4[i] = g_att[((size_t)b*F_ + f) * T_ + i*128 + t];

    __syncthreads();   // W/pwT/thr staged (both groups)

    // warp HMMA geometry
    const int wm = wid & 3;
    const int wn = wid >> 2;
    const int quad = lane >> 3, r8 = lane & 7;
    const int arow = (quad & 1) ? 8 : 0;
    const int akof = (quad & 2) ? 16 : 0;
    const uint32_t aH0 = s0 + AH_OFF + (unsigned)(wm*32 + arow + r8) * 272u + akof;
    const uint32_t aH1 = aH0 + 16u * 272u;
    const int brow = (quad & 2) ? 8 : 0;
    const int bkof = (quad & 1) ? 16 : 0;
    const uint32_t bH0 = s0 + WH_OFF + (unsigned)(wn*32 + brow + r8) * 272u + bkof;
    const uint32_t bH1 = bH0 + 16u * 272u;

    const int BX = 3 + g, BY = 5 + g;       // group-local barrier ids
    GBAR_ARRIVE(BY);

    for (int tt = 0; tt < 4; tt++) {
        const int t0 = tt * 128;

        GBAR_WAIT(BY);   // group's ldsm of previous tile done -> safe to overwrite A half

        // ---- build A half-tile: RN fp16, direct LDG (occupancy hides latency) ----
        {
            float a = a4[tt];
            const float* thrS = (const float*)(sm + THR_OFF);
            int Kc = 0;
            #pragma unroll
            for (int i = 0; i < NTHR_; i++) Kc += (a > thrS[i]) ? 1 : 0;
            const float* pwRow = (const float*)(sm + PW_OFF) + Kc * 68;
            const float* xp = xbase + t0;

            char* rowH = sm + AH_OFF + (unsigned)t * 272u;
            #pragma unroll
            for (int c4 = 0; c4 < 32; c4 += 4) {
                int c = ch + c4;
                float4 pw4 = *(const float4*)(pwRow + c);
                float v[4], av[4];
                #pragma unroll
                for (int j = 0; j < 4; j++) v[j] = __ldg(xp + (size_t)(c + j) * FT_);
                av[0] = (a * pw4.x) * v[0];
                av[1] = (a * pw4.y) * v[1];
                av[2] = (a * pw4.z) * v[2];
                av[3] = (a * pw4.w) * v[3];
                uint2 ph  = make_uint2(pack_h2(v[0],  v[1]),  pack_h2(v[2],  v[3]));
                uint2 pah = make_uint2(pack_h2(av[0], av[1]), pack_h2(av[2], av[3]));
                *(uint2*)(rowH + c*2)       = ph;
                *(uint2*)(rowH + 128 + c*2) = pah;
            }
        }
        GBAR_ARRIVE(BX);   // my STS done
        GBAR_WAIT(BX);     // group's STS done -> A half complete

        // ---- HMMA: single fp16 pass, 64 mma ----
        float acc[2][4][4];
        #pragma unroll
        for (int ms = 0; ms < 2; ms++)
            #pragma unroll
            for (int nb = 0; nb < 4; nb++)
                #pragma unroll
                for (int e = 0; e < 4; e++) acc[ms][nb][e] = 0.f;

        #pragma unroll 4
        for (int ks = 0; ks < 8; ks++) {
            const uint32_t ko = (unsigned)ks * 32u;
            uint32_t ah[2][4], bh[2][4];
            ldsm_x4(ah[0], aH0 + ko);
            ldsm_x4(ah[1], aH1 + ko);
            ldsm_x4(bh[0], bH0 + ko);
            ldsm_x4(bh[1], bH1 + ko);
            #pragma unroll
            for (int ms = 0; ms < 2; ms++) {
                #pragma unroll
                for (int nb = 0; nb < 4; nb++) {
                    mma16816(acc[ms][nb], ah[ms], &bh[nb >> 1][(nb & 1) * 2]);
                }
            }
        }
        GBAR_ARRIVE(BY);   // my ldsm reads of A half done -> epilogue off the critical path

        // ---- fp16 half2 epilogue: g_o16[b][f][t][c], channel-pair packed STG.32 ----
        {
            const float* bosS = (const float*)(sm + BOS_OFF);
            const int r = lane >> 2;
            __half* gob = g_o16 + ((size_t)(b*256 + f)*512 + (unsigned)(t0 + wm*32)) * 64;
            #pragma unroll
            for (int nb = 0; nb < 4; nb++) {
                int c = wn*32 + nb*8 + 2*(lane & 3);
                float b0 = bosS[c], b1 = bosS[c+1];
                float v00 = acc[0][nb][0] + b0, v01 = acc[0][nb][1] + b1;
                float v02 = acc[0][nb][2] + b0, v03 = acc[0][nb][3] + b1;
                float v10 = acc[1][nb][0] + b0, v11 = acc[1][nb][1] + b1;
                float v12 = acc[1][nb][2] + b0, v13 = acc[1][nb][3] + b1;
                *(unsigned*)(gob + (size_t)(r     )*64 + c) = pack_h2(v00, v01);
                *(unsigned*)(gob + (size_t)(r +  8)*64 + c) = pack_h2(v02, v03);
                *(unsigned*)(gob + (size_t)(r + 16)*64 + c) = pack_h2(v10, v11);
                *(unsigned*)(gob + (size_t)(r + 24)*64 + c) = pack_h2(v12, v13);
                float s0c = (v00 + v02) + (v10 + v12);
                float s1c = (v01 + v03) + (v11 + v13);
                float q0c = (v00*v00 + v02*v02) + (v10*v10 + v12*v12);
                float q1c = (v01*v01 + v03*v03) + (v11*v11 + v13*v13);
                #pragma unroll
                for (int m = 4; m < 32; m <<= 1) {
                    s0c += __shfl_xor_sync(0xffffffffu, s0c, m);
                    s1c += __shfl_xor_sync(0xffffffffu, s1c, m);
                    q0c += __shfl_xor_sync(0xffffffffu, q0c, m);
                    q1c += __shfl_xor_sync(0xffffffffu, q1c, m);
                }
                if (lane < 4) {
                    size_t prow = ((((size_t)(b*256 + f))*4 + tt)*4 + wm) * 128;
                    g_part[prow + c]          = s0c;
                    g_part[prow + c + 1]      = s1c;
                    g_part[prow + 64 + c]     = q0c;
                    g_part[prow + 64 + c + 1] = q1c;
                }
            }
        }
    }
}

// ---------------- K5a: parallel partial reduce (128 CTAs, 256 rows each) ----------------
__global__ void k_stats1() {
    int j = threadIdx.x;           // 0..127
    size_t r0 = (size_t)blockIdx.x * 256;
    float s = 0.f;
    #pragma unroll 8
    for (int r = 0; r < 256; r++) s += g_part[(r0 + r)*128 + j];
    g_part2[blockIdx.x*128 + j] = s;
}

// ---------------- K5b: final stats (1 CTA, double) ----------------
__global__ void k_stats2(const float* __restrict__ gamma, const float* __restrict__ beta) {
    __shared__ double acc[128];
    int j = threadIdx.x;           // 0..127
    double s = 0.0;
    for (int i = 0; i < 128; i++) s += (double)g_part2[i*128 + j];
    acc[j] = s;
    __syncthreads();
    if (j < 64) {
        double mu  = acc[j] / NPOSF;
        double var = acc[64 + j] / NPOSF - mu * mu;
        float sc = gamma[j] * (float)(1.0 / sqrt(var + 1e-5));
        g_scale[j] = sc;
        g_shift[j] = beta[j] - (float)mu * sc;
    }
}

// ---------------- K6: normalize + ReLU + transpose [t][c] -> [c][f][t], fp16 in ----------------
__global__ void k_norm(float* __restrict__ out) {
    __shared__ float sc[64], sh[64];
    __shared__ float tilebuf[128*64];
    const int bx = blockIdx.x;
    const int plane = bx >> 2, tq4 = bx & 3;
    const int b = plane >> 8, f = plane & 255;
    const int t0 = tq4 * 128;
    const int tid = threadIdx.x;
    const int lane = tid & 31;
    const int wid = tid >> 5;
    if (tid < 64) { sc[tid] = g_scale[tid]; sh[tid] = g_shift[tid]; }
    // phase 1: read fp16 tile coalesced (uint4 = 8 halves), unpack, store swizzled fp32
    const uint4* src = (const uint4*)(g_o16 + ((size_t)plane*512 + t0) * 64);
    for (int i = tid; i < 1024; i += 256) {
        int t = i >> 3, c8 = i & 7;
        uint4 v = src[t*8 + c8];
        float2 f0 = __half22float2(*(__half2*)&v.x);
        float2 f1 = __half22float2(*(__half2*)&v.y);
        float2 f2 = __half22float2(*(__half2*)&v.z);
        float2 f3 = __half22float2(*(__half2*)&v.w);
        int ga = (2*c8     + t + (t >> 4)) & 15;
        int gb = (2*c8 + 1 + t + (t >> 4)) & 15;
        *(float4*)&tilebuf[t*64 + ga*4] = make_float4(f0.x, f0.y, f1.x, f1.y);
        *(float4*)&tilebuf[t*64 + gb*4] = make_float4(f2.x, f2.y, f3.x, f3.y);
    }
    __syncthreads();
    // phase 2: warp-per-channel; lane l covers t=4l..4l+3 -> one STG.128 (validated R10 code)
    #pragma unroll
    for (int p = 0; p < 8; p++) {
        const int c = p*8 + wid;
        const float s = sc[c], h = sh[c];
        const int k = c >> 2, cj = c & 3;
        float4 o;
        #pragma unroll
        for (int e = 0; e < 4; e++) {
            int t = 4*lane + e;
            int g = (k + t + (t >> 4)) & 15;
            float v = tilebuf[t*64 + g*4 + cj];
            ((float*)&o)[e] = fmaxf(fmaf(v, s, h), 0.f);
        }
        *(float4*)(out + ((size_t)(b*64 + c)*256 + f)*512 + t0 + 4*lane) = o;
    }
}

// ---------------- launch ----------------
extern "C" void kernel_launch(void* const* d_in, const int* in_sizes, int n_in,
                              void* d_out, int out_size) {
    const float* x     = (const float*)d_in[0];
    const float* w1    = (const float*)d_in[1];
    const float* b1    = (const float*)d_in[2];
    const float* w2    = (const float*)d_in[3];
    const float* b2    = (const float*)d_in[4];
    const float* wc    = (const float*)d_in[5];
    const float* bc    = (const float*)d_in[6];
    const float* wc2   = (const float*)d_in[7];
    const float* bc2   = (const float*)d_in[8];
    const float* wo    = (const float*)d_in[9];
    const float* bo    = (const float*)d_in[10];
    const float* gamma = (const float*)d_in[11];
    const float* beta  = (const float*)d_in[12];
    float* out = (float*)d_out;

    cudaFuncSetAttribute(k_main, cudaFuncAttributeMaxDynamicSharedMemorySize, K4_SMEM);

    k_reduce_prep<<<513, 256>>>(x, wc2, bc2, wo);
    k_mlp<<<dim3(768, B_), 64>>>(w1, b1, w2, b2);
    k_attmap<<<dim3(F_/8, B_), 256>>>(wc, bc);
    k_main<<<dim3(F_, B_), 256, K4_SMEM>>>(x, bo);
    k_stats1<<<128, 128>>>();
    k_stats2<<<1, 128>>>(gamma, beta);
    k_norm<<<8192, 256>>>(out);
}